// round 1
// baseline (speedup 1.0000x reference)
#include <cuda_runtime.h>
#include <cuda_bf16.h>
#include <cstdio>

// Problem constants
#define PB   2            // batch
#define PN   150000       // points per sample
#define PC   64           // channels
#define PD   128          // grid extent
#define PD3  (PD*PD*PD)   // 2097152
#define BN   (PB*PN)      // 300000
#define TOTE (BN*PC)      // 19,200,000 elements per feature tensor
#define EPSV 1e-4f

#define STAT_BLOCKS 512
#define TILE 128
#define SF_STRIDE 65

// ----------------------------------------------------------------------------
// Scratch (device globals; no allocation allowed)
// ----------------------------------------------------------------------------
__device__ int   g_lut[PB * PD3];            // 16.8 MB
__device__ int   g_nbr[27 * BN];             // 32.4 MB, layout [k][b*N+n] for coalesced tap reads
__device__ float g_tmp1[(size_t)BN * PC];    // 76.8 MB
__device__ float g_tmp2[(size_t)BN * PC];    // 76.8 MB
__device__ float g_part[2 * STAT_BLOCKS * PC];
__device__ float g_scale[PC];
__device__ float g_shift[PC];

// ----------------------------------------------------------------------------
// LUT build
// ----------------------------------------------------------------------------
__global__ void fill_lut_kernel() {
    int i = blockIdx.x * blockDim.x + threadIdx.x;
    if (i < PB * PD3) g_lut[i] = -1;
}

__global__ void scatter_lut_kernel(const int* __restrict__ pos) {
    int i = blockIdx.x * blockDim.x + threadIdx.x;
    if (i >= BN) return;
    int b = i / PN;
    int n = i - b * PN;
    int px = pos[3 * i + 0];
    int py = pos[3 * i + 1];
    int pz = pos[3 * i + 2];
    int code = (px * PD + py) * PD + pz;
    g_lut[b * PD3 + code] = n;
}

// Neighbor indices for all 27 taps, stored transposed: g_nbr[k*BN + (b*N+n)]
__global__ void build_nbr_kernel(const int* __restrict__ pos) {
    int i = blockIdx.x * blockDim.x + threadIdx.x;
    if (i >= BN) return;
    int b = i / PN;
    int px = pos[3 * i + 0];
    int py = pos[3 * i + 1];
    int pz = pos[3 * i + 2];
    const int* lutb = g_lut + b * PD3;
#pragma unroll
    for (int k = 0; k < 27; k++) {
        int dx = k / 9 - 1;
        int dy = (k / 3) % 3 - 1;
        int dz = k % 3 - 1;
        int nx = px + dx, ny = py + dy, nz = pz + dz;
        int nidx = -1;
        if (((unsigned)nx < PD) & ((unsigned)ny < PD) & ((unsigned)nz < PD)) {
            nidx = lutb[(nx * PD + ny) * PD + nz];
        }
        g_nbr[k * BN + i] = nidx;
    }
}

// ----------------------------------------------------------------------------
// BatchNorm statistics (deterministic two-stage reduction) + ReLU apply
// ----------------------------------------------------------------------------
__global__ void stats_kernel(const float* __restrict__ x) {
    __shared__ float ss[256];
    __shared__ float sq[256];
    int c  = threadIdx.x & 63;
    int rg = threadIdx.x >> 6;   // 0..3
    float s = 0.f, q = 0.f;
    for (int row = blockIdx.x * 4 + rg; row < BN; row += gridDim.x * 4) {
        float v = x[(size_t)row * PC + c];
        s += v;
        q += v * v;
    }
    ss[threadIdx.x] = s;
    sq[threadIdx.x] = q;
    __syncthreads();
    if (threadIdx.x < 64) {
        s = ss[c] + ss[c + 64] + ss[c + 128] + ss[c + 192];
        q = sq[c] + sq[c + 64] + sq[c + 128] + sq[c + 192];
        g_part[blockIdx.x * PC + c] = s;
        g_part[STAT_BLOCKS * PC + blockIdx.x * PC + c] = q;
    }
}

__global__ void finalize_stats_kernel(const float* __restrict__ gamma,
                                      const float* __restrict__ beta) {
    int c = threadIdx.x;  // 64 threads
    float s = 0.f, q = 0.f;
    for (int b = 0; b < STAT_BLOCKS; b++) {
        s += g_part[b * PC + c];
        q += g_part[STAT_BLOCKS * PC + b * PC + c];
    }
    const float inv = 1.0f / (float)BN;
    float mu  = s * inv;
    float var = q * inv - mu * mu;
    float rstd = rsqrtf(var + EPSV);
    float sc = rstd * gamma[c];
    g_scale[c] = sc;
    g_shift[c] = beta[c] - mu * sc;
}

__global__ void bnrelu_kernel(const float* __restrict__ x, float* __restrict__ y) {
    int i = blockIdx.x * blockDim.x + threadIdx.x;
    if (i >= TOTE) return;
    int c = i & 63;
    y[i] = fmaxf(fmaf(x[i], g_scale[c], g_shift[c]), 0.f);
}

__global__ void add_kernel(float* __restrict__ x, const float* __restrict__ y) {
    int i = blockIdx.x * blockDim.x + threadIdx.x;
    if (i >= TOTE) return;
    x[i] += y[i];
}

// ----------------------------------------------------------------------------
// Submanifold conv: per 128-point tile, 27 taps, gather + 64x64 GEMM (fp32)
//   dyn smem: sW[64*64] then sF[128*65]
// ----------------------------------------------------------------------------
extern __shared__ float s_dyn[];

__global__ __launch_bounds__(256) void conv_kernel(const float* __restrict__ h,
                                                   const float* __restrict__ Wall,
                                                   float* __restrict__ out) {
    float* sW = s_dyn;              // 64*64
    float* sF = s_dyn + 64 * 64;    // 128 * SF_STRIDE

    const int b   = blockIdx.y;
    const int pt0 = blockIdx.x * TILE;
    const int tid = threadIdx.x;
    const int grp = tid >> 3;          // 0..31 -> owns 4 points
    const int ocb = (tid & 7) * 8;     // out-channel base

    // gather role
    const int gpt  = tid & 127;        // point within tile
    const int half = tid >> 7;         // channel half (0: 0-31, 1: 32-63)
    const int gp_global = pt0 + gpt;
    const bool gvalid = (gp_global < PN);

    float acc[4][8];
#pragma unroll
    for (int i = 0; i < 4; i++)
#pragma unroll
        for (int j = 0; j < 8; j++) acc[i][j] = 0.f;

    for (int k = 0; k < 27; k++) {
        // stage W_k (64x64) into shared, 4 float4 per thread
        const float4* Wk = (const float4*)(Wall + k * 4096);
        float4* sW4 = (float4*)sW;
#pragma unroll
        for (int i = 0; i < 4; i++) sW4[tid + 256 * i] = Wk[tid + 256 * i];

        // gather neighbor feature rows (128 pts x 64ch), scalar stores (bank-clean)
        {
            int nidx = -1;
            if (gvalid) nidx = g_nbr[k * BN + b * PN + gp_global];
            float* dst = &sF[gpt * SF_STRIDE + half * 32];
            if (nidx >= 0) {
                const float4* src =
                    (const float4*)(h + ((size_t)b * PN + nidx) * PC + half * 32);
#pragma unroll
                for (int m = 0; m < 8; m++) {
                    float4 v = src[m];
                    dst[4 * m + 0] = v.x;
                    dst[4 * m + 1] = v.y;
                    dst[4 * m + 2] = v.z;
                    dst[4 * m + 3] = v.w;
                }
            } else {
#pragma unroll
                for (int m = 0; m < 32; m++) dst[m] = 0.f;
            }
        }
        __syncthreads();

        // 128x64x64 tile GEMM accumulate
#pragma unroll 8
        for (int ci = 0; ci < 64; ci++) {
            const float4 w0 = *(const float4*)(sW + ci * 64 + ocb);
            const float4 w1 = *(const float4*)(sW + ci * 64 + ocb + 4);
#pragma unroll
            for (int i = 0; i < 4; i++) {
                const float f = sF[(grp * 4 + i) * SF_STRIDE + ci];
                acc[i][0] = fmaf(f, w0.x, acc[i][0]);
                acc[i][1] = fmaf(f, w0.y, acc[i][1]);
                acc[i][2] = fmaf(f, w0.z, acc[i][2]);
                acc[i][3] = fmaf(f, w0.w, acc[i][3]);
                acc[i][4] = fmaf(f, w1.x, acc[i][4]);
                acc[i][5] = fmaf(f, w1.y, acc[i][5]);
                acc[i][6] = fmaf(f, w1.z, acc[i][6]);
                acc[i][7] = fmaf(f, w1.w, acc[i][7]);
            }
        }
        __syncthreads();
    }

    // write 4 points x 8 channels
#pragma unroll
    for (int i = 0; i < 4; i++) {
        int pt = pt0 + grp * 4 + i;
        if (pt < PN) {
            float4* o = (float4*)(out + ((size_t)b * PN + pt) * PC + ocb);
            o[0] = make_float4(acc[i][0], acc[i][1], acc[i][2], acc[i][3]);
            o[1] = make_float4(acc[i][4], acc[i][5], acc[i][6], acc[i][7]);
        }
    }
}

// ----------------------------------------------------------------------------
// Host orchestration
// ----------------------------------------------------------------------------
static void run_bn(const float* xin, float* yout, const float* gamma, const float* beta) {
    stats_kernel<<<STAT_BLOCKS, 256>>>(xin);
    finalize_stats_kernel<<<1, 64>>>(gamma, beta);
    bnrelu_kernel<<<(TOTE + 255) / 256, 256>>>(xin, yout);
}

extern "C" void kernel_launch(void* const* d_in, const int* in_sizes, int n_in,
                              void* d_out, int out_size) {
    const float* feats  = (const float*)d_in[0];  // [2,150000,64]
    const float* Ws     = (const float*)d_in[1];  // [4,27,64,64]
    const float* gammas = (const float*)d_in[2];  // [4,64]
    const float* betas  = (const float*)d_in[3];  // [4,64]
    const int*   pos    = (const int*)d_in[4];    // [2,150000,3]
    float* x = (float*)d_out;                     // [2,150000,64]

    float *tmp1, *tmp2;
    cudaGetSymbolAddress((void**)&tmp1, g_tmp1);
    cudaGetSymbolAddress((void**)&tmp2, g_tmp2);

    const int smem = (64 * 64 + TILE * SF_STRIDE) * (int)sizeof(float);  // 49664 B
    static bool attr_set = false;
    // idempotent; cheap to call every time, and safe under graph capture
    cudaFuncSetAttribute(conv_kernel, cudaFuncAttributeMaxDynamicSharedMemorySize, smem);
    (void)attr_set;

    // x = feats
    cudaMemcpyAsync(x, feats, (size_t)TOTE * sizeof(float), cudaMemcpyDeviceToDevice, 0);

    // LUT + neighbor table (built once, reused by all 4 convs)
    fill_lut_kernel<<<(PB * PD3 + 1023) / 1024, 1024>>>();
    scatter_lut_kernel<<<(BN + 255) / 256, 256>>>(pos);
    build_nbr_kernel<<<(BN + 255) / 256, 256>>>(pos);

    dim3 cgrid((PN + TILE - 1) / TILE, PB);

    for (int blk = 0; blk < 2; blk++) {
        // h = bn_relu(x) -> tmp1
        run_bn(x, tmp1, gammas + (2 * blk) * PC, betas + (2 * blk) * PC);
        // tmp2 = conv(tmp1, W[2blk])
        conv_kernel<<<cgrid, 256, smem>>>(tmp1, Ws + (size_t)(2 * blk) * 27 * 4096, tmp2);
        // tmp1 = bn_relu(tmp2)
        run_bn(tmp2, tmp1, gammas + (2 * blk + 1) * PC, betas + (2 * blk + 1) * PC);
        // tmp2 = conv(tmp1, W[2blk+1])
        conv_kernel<<<cgrid, 256, smem>>>(tmp1, Ws + (size_t)(2 * blk + 1) * 27 * 4096, tmp2);
        // x += tmp2
        add_kernel<<<(TOTE + 255) / 256, 256>>>(x, tmp2);
    }
}

// round 3
// speedup vs baseline: 3.1107x; 3.1107x over previous
#include <cuda_runtime.h>
#include <cstdint>

// Problem constants
#define PB   2
#define PN   150000
#define PC   64
#define PD   128
#define PD3  (PD*PD*PD)
#define BN   (PB*PN)
#define TOTE (BN*PC)
#define EPSV 1e-4f
#define STAT_BLOCKS 1024

#define TILE_M 256
#define NTILES ((PN + TILE_M - 1) / TILE_M)   // 586

// smem layout for conv kernel
#define SA_STRIDE 68
#define SA_BYTES  (TILE_M * SA_STRIDE * 4)    // 69632
#define SW_BYTES  (64 * SA_STRIDE * 4)        // 17408
#define OFF_A(s)  ((s) * SA_BYTES)
#define OFF_W(s)  (2 * SA_BYTES + (s) * SW_BYTES)
#define OFF_FLAG  (2 * SA_BYTES + 2 * SW_BYTES)   // 174080
#define SMEM_TOTAL (OFF_FLAG + 128)               // 174208

// ---------------- device scratch (no allocation allowed) ----------------
__device__ int   g_lut[PB * PD3];
__device__ int   g_nbr[27 * BN];
__device__ float g_tmp1[(size_t)BN * PC];
__device__ float g_tmp2[(size_t)BN * PC];
__device__ float g_wt[4 * 27 * PC * PC];     // tf32-rounded copy of Ws (same layout)
__device__ float g_part[2 * STAT_BLOCKS * PC];
__device__ float g_scale[PC];
__device__ float g_shift[PC];

// ---------------- helpers ----------------
__device__ __forceinline__ uint32_t smem_u32(const void* p) {
    uint32_t a;
    asm("{ .reg .u64 t; cvta.to.shared.u64 t, %1; cvt.u32.u64 %0, t; }" : "=r"(a) : "l"(p));
    return a;
}
__device__ __forceinline__ float tf32r(float x) {
    uint32_t u;
    asm("cvt.rna.tf32.f32 %0, %1;" : "=r"(u) : "f"(x));
    return __uint_as_float(u);
}

// ---------------- prep kernels ----------------
__global__ void fill_lut_kernel() {
    int i = blockIdx.x * blockDim.x + threadIdx.x;
    if (i < PB * PD3) g_lut[i] = -1;
}
__global__ void scatter_lut_kernel(const int* __restrict__ pos) {
    int i = blockIdx.x * blockDim.x + threadIdx.x;
    if (i >= BN) return;
    int b = i / PN;
    int code = (pos[3 * i] * PD + pos[3 * i + 1]) * PD + pos[3 * i + 2];
    g_lut[b * PD3 + code] = i - b * PN;
}
__global__ void build_nbr_kernel(const int* __restrict__ pos) {
    int i = blockIdx.x * blockDim.x + threadIdx.x;
    if (i >= BN) return;
    int b = i / PN;
    int px = pos[3 * i], py = pos[3 * i + 1], pz = pos[3 * i + 2];
    const int* lutb = g_lut + b * PD3;
#pragma unroll
    for (int k = 0; k < 27; k++) {
        int nx = px + k / 9 - 1, ny = py + (k / 3) % 3 - 1, nz = pz + k % 3 - 1;
        int nidx = -1;
        if (((unsigned)nx < PD) & ((unsigned)ny < PD) & ((unsigned)nz < PD))
            nidx = lutb[(nx * PD + ny) * PD + nz];
        g_nbr[k * BN + i] = nidx;
    }
}
__global__ void wprep_kernel(const float* __restrict__ Ws) {
    int i = blockIdx.x * blockDim.x + threadIdx.x;
    if (i < 4 * 27 * 4096) g_wt[i] = tf32r(Ws[i]);
}

// ---------------- BN ----------------
__global__ void stats_kernel(const float* __restrict__ x) {
    __shared__ float red[2048];
    int t = threadIdx.x;
    size_t gid = (size_t)blockIdx.x * 256 + t;
    const float4* x4 = (const float4*)x;
    float4 s = make_float4(0, 0, 0, 0), q = make_float4(0, 0, 0, 0);
    for (size_t i = gid; i < (size_t)TOTE / 4; i += (size_t)256 * STAT_BLOCKS) {
        float4 v = x4[i];
        s.x += v.x; s.y += v.y; s.z += v.z; s.w += v.w;
        q.x += v.x * v.x; q.y += v.y * v.y; q.z += v.z * v.z; q.w += v.w * v.w;
    }
    red[t * 4 + 0] = s.x; red[t * 4 + 1] = s.y; red[t * 4 + 2] = s.z; red[t * 4 + 3] = s.w;
    red[1024 + t * 4 + 0] = q.x; red[1024 + t * 4 + 1] = q.y;
    red[1024 + t * 4 + 2] = q.z; red[1024 + t * 4 + 3] = q.w;
    __syncthreads();
    if (t < 64) {
        int comp = t & 3, grp = t >> 2;
        float S = 0.f, Q = 0.f;
#pragma unroll
        for (int m = 0; m < 16; m++) {
            int o = grp + m * 16;
            S += red[o * 4 + comp];
            Q += red[1024 + o * 4 + comp];
        }
        g_part[blockIdx.x * 64 + t] = S;
        g_part[STAT_BLOCKS * 64 + blockIdx.x * 64 + t] = Q;
    }
}

__global__ void finalize_stats_kernel(const float* __restrict__ gamma,
                                      const float* __restrict__ beta) {
    __shared__ float r[512];
    int t = threadIdx.x;            // 256
    int c = t & 63, seg = t >> 6;
    float S = 0.f, Q = 0.f;
    for (int b = seg * 256; b < (seg + 1) * 256; b++) {
        S += g_part[b * 64 + c];
        Q += g_part[STAT_BLOCKS * 64 + b * 64 + c];
    }
    r[t] = S; r[256 + t] = Q;
    __syncthreads();
    if (t < 64) {
        float s = r[t] + r[t + 64] + r[t + 128] + r[t + 192];
        float q = r[256 + t] + r[256 + t + 64] + r[256 + t + 128] + r[256 + t + 192];
        const float inv = 1.0f / (float)BN;
        float mu = s * inv;
        float var = q * inv - mu * mu;
        float rstd = rsqrtf(var + EPSV);
        float sc = rstd * gamma[t];
        g_scale[t] = sc;
        g_shift[t] = beta[t] - mu * sc;
    }
}

__global__ void bnrelu_kernel(const float* __restrict__ x, float* __restrict__ y) {
    int i = blockIdx.x * blockDim.x + threadIdx.x;
    if (i >= TOTE / 4) return;
    float4 v = ((const float4*)x)[i];
    int c4 = i & 15;
    float4 sc = ((const float4*)g_scale)[c4];
    float4 sh = ((const float4*)g_shift)[c4];
    v.x = tf32r(fmaxf(fmaf(v.x, sc.x, sh.x), 0.f));
    v.y = tf32r(fmaxf(fmaf(v.y, sc.y, sh.y), 0.f));
    v.z = tf32r(fmaxf(fmaf(v.z, sc.z, sh.z), 0.f));
    v.w = tf32r(fmaxf(fmaf(v.w, sc.w, sh.w), 0.f));
    ((float4*)y)[i] = v;
}

// ---------------- tensor-core conv via mma.sync (tf32) ----------------
// CTA: 256 points x 64 out-ch. 512 threads = 16 warps (8 M-groups x 2 N-halves).
// Each warp: 32x32 output tile = 2 m16 x 4 n8 mma tiles, K=64 per tap, 27 taps.
// A (gathered features) and W double-buffered in smem via cp.async with
// zero-fill (src-size 0) for absent neighbors.
__global__ __launch_bounds__(512, 1) void conv_mma_kernel(
    const float* __restrict__ h, const float* __restrict__ wt,
    float* __restrict__ out, const float* __restrict__ addsrc) {
    extern __shared__ char smem[];
    const uint32_t sbase = smem_u32(smem);
    const int tid  = threadIdx.x;
    const int lane = tid & 31;
    const int wid  = tid >> 5;
    const int b    = blockIdx.y;
    const int pt0  = blockIdx.x * TILE_M;
    const float* hb = h + (size_t)b * PN * PC;
    int* flags = (int*)(smem + OFF_FLAG);   // [2][16]

    const int warp_m = wid >> 1;    // 0..7 (32-row group)
    const int warp_n = wid & 1;     // 0..1 (32-col half)
    const int g   = lane >> 2;      // 0..7
    const int tig = lane & 3;       // 0..3

    float acc[2][4][4];
#pragma unroll
    for (int mt = 0; mt < 2; mt++)
#pragma unroll
        for (int nt = 0; nt < 4; nt++)
#pragma unroll
            for (int e = 0; e < 4; e++) acc[mt][nt][e] = 0.f;

    // ---- tap gather: A rows (cp.async, zero-fill invalid) + W tile ----
    auto issue = [&](int k, int s) {
        int row  = tid >> 1;
        int p    = pt0 + row;
        int nidx = (p < PN) ? g_nbr[k * BN + b * PN + p] : -1;
        unsigned msk = __ballot_sync(0xffffffffu, nidx >= 0);
        if (lane == 0) flags[s * 16 + wid] = (msk != 0u);
        const char* src = (const char*)(hb + (size_t)(nidx < 0 ? 0 : nidx) * PC)
                          + (tid & 1) * 128;
        uint32_t dst = sbase + OFF_A(s) + row * (SA_STRIDE * 4) + (tid & 1) * 128;
        int ssz = (nidx >= 0) ? 16 : 0;
#pragma unroll
        for (int c = 0; c < 8; c++)
            asm volatile("cp.async.ca.shared.global [%0], [%1], 16, %2;"
                         :: "r"(dst + c * 16), "l"(src + c * 16), "r"(ssz));
        // W: 64x64 floats, 1024 16B-chunks, 2 per thread
        {
            int wrow = tid >> 3;
            int wc   = (tid & 7) * 2;
            const char* ws = (const char*)(wt + (size_t)k * 4096) + wrow * 256 + wc * 16;
            uint32_t wdst = sbase + OFF_W(s) + wrow * (SA_STRIDE * 4) + wc * 16;
            asm volatile("cp.async.ca.shared.global [%0], [%1], 16;" :: "r"(wdst), "l"(ws));
            asm volatile("cp.async.ca.shared.global [%0], [%1], 16;" :: "r"(wdst + 16), "l"(ws + 16));
        }
        asm volatile("cp.async.commit_group;" ::: "memory");
    };

    // ---- tap compute: 2x4 mma tiles over 8 K-steps ----
    auto compute = [&](int s) {
        int f = flags[s * 16 + 2 * warp_m] | flags[s * 16 + 2 * warp_m + 1];
        if (!f) return;
        const float* A  = (const float*)(smem + OFF_A(s)) + (warp_m * 32 + g) * SA_STRIDE;
        const float* Wm = (const float*)(smem + OFF_W(s)) + warp_n * 32 + g;
#pragma unroll
        for (int k8 = 0; k8 < 8; k8++) {
            uint32_t a[2][4], bb[4][2];
#pragma unroll
            for (int mt = 0; mt < 2; mt++) {
                const float* Ab = A + mt * 16 * SA_STRIDE + k8 * 8;
                a[mt][0] = __float_as_uint(Ab[tig]);
                a[mt][1] = __float_as_uint(Ab[8 * SA_STRIDE + tig]);
                a[mt][2] = __float_as_uint(Ab[tig + 4]);
                a[mt][3] = __float_as_uint(Ab[8 * SA_STRIDE + tig + 4]);
            }
#pragma unroll
            for (int nt = 0; nt < 4; nt++) {
                const float* Wb = Wm + (k8 * 8 + tig) * SA_STRIDE + nt * 8;
                bb[nt][0] = __float_as_uint(Wb[0]);
                bb[nt][1] = __float_as_uint(Wb[4 * SA_STRIDE]);
            }
#pragma unroll
            for (int mt = 0; mt < 2; mt++)
#pragma unroll
                for (int nt = 0; nt < 4; nt++)
                    asm volatile(
                        "mma.sync.aligned.m16n8k8.row.col.f32.tf32.tf32.f32 "
                        "{%0,%1,%2,%3}, {%4,%5,%6,%7}, {%8,%9}, {%0,%1,%2,%3};"
                        : "+f"(acc[mt][nt][0]), "+f"(acc[mt][nt][1]),
                          "+f"(acc[mt][nt][2]), "+f"(acc[mt][nt][3])
                        : "r"(a[mt][0]), "r"(a[mt][1]), "r"(a[mt][2]), "r"(a[mt][3]),
                          "r"(bb[nt][0]), "r"(bb[nt][1]));
        }
    };

    issue(0, 0);
    for (int k = 0; k < 27; k++) {
        const int s = k & 1;
        if (k + 1 < 27) {
            issue(k + 1, s ^ 1);
            asm volatile("cp.async.wait_group 1;" ::: "memory");
        } else {
            asm volatile("cp.async.wait_group 0;" ::: "memory");
        }
        __syncthreads();
        compute(s);
        __syncthreads();
    }

    // ---- epilogue: write 32x32 per warp, optional residual add ----
    const bool doadd = (addsrc != nullptr);
#pragma unroll
    for (int mt = 0; mt < 2; mt++) {
#pragma unroll
        for (int half = 0; half < 2; half++) {
            int r = warp_m * 32 + mt * 16 + half * 8 + g;
            int p = pt0 + r;
            if (p < PN) {
                size_t rowoff = ((size_t)b * PN + p) * PC + warp_n * 32 + 2 * tig;
                float* orow = out + rowoff;
#pragma unroll
                for (int nt = 0; nt < 4; nt++) {
                    float2 v;
                    v.x = acc[mt][nt][half * 2 + 0];
                    v.y = acc[mt][nt][half * 2 + 1];
                    if (doadd) {
                        float2 av = *(const float2*)(addsrc + rowoff + nt * 8);
                        v.x += av.x; v.y += av.y;
                    }
                    *(float2*)(orow + nt * 8) = v;
                }
            }
        }
    }
}

// ---------------- host orchestration ----------------
static void run_bn(const float* xin, float* yout, const float* gamma, const float* beta) {
    stats_kernel<<<STAT_BLOCKS, 256>>>(xin);
    finalize_stats_kernel<<<1, 256>>>(gamma, beta);
    bnrelu_kernel<<<(TOTE / 4 + 255) / 256, 256>>>(xin, yout);
}

extern "C" void kernel_launch(void* const* d_in, const int* in_sizes, int n_in,
                              void* d_out, int out_size) {
    const float* feats  = (const float*)d_in[0];
    const float* Ws     = (const float*)d_in[1];
    const float* gammas = (const float*)d_in[2];
    const float* betas  = (const float*)d_in[3];
    const int*   pos    = (const int*)d_in[4];
    float* x = (float*)d_out;

    float *tmp1, *tmp2, *wt;
    cudaGetSymbolAddress((void**)&tmp1, g_tmp1);
    cudaGetSymbolAddress((void**)&tmp2, g_tmp2);
    cudaGetSymbolAddress((void**)&wt, g_wt);

    cudaFuncSetAttribute(conv_mma_kernel, cudaFuncAttributeMaxDynamicSharedMemorySize,
                         SMEM_TOTAL);

    cudaMemcpyAsync(x, feats, (size_t)TOTE * sizeof(float), cudaMemcpyDeviceToDevice, 0);

    fill_lut_kernel<<<(PB * PD3 + 1023) / 1024, 1024>>>();
    scatter_lut_kernel<<<(BN + 255) / 256, 256>>>(pos);
    build_nbr_kernel<<<(BN + 255) / 256, 256>>>(pos);
    wprep_kernel<<<(4 * 27 * 4096 + 255) / 256, 256>>>(Ws);

    dim3 cgrid(NTILES, PB);

    for (int blk = 0; blk < 2; blk++) {
        run_bn(x, tmp1, gammas + (2 * blk) * PC, betas + (2 * blk) * PC);
        conv_mma_kernel<<<cgrid, 512, SMEM_TOTAL>>>(
            tmp1, wt + (size_t)(2 * blk) * 27 * 4096, tmp2, nullptr);
        run_bn(tmp2, tmp1, gammas + (2 * blk + 1) * PC, betas + (2 * blk + 1) * PC);
        conv_mma_kernel<<<cgrid, 512, SMEM_TOTAL>>>(
            tmp1, wt + (size_t)(2 * blk + 1) * 27 * 4096, x, x);
    }
}

// round 4
// speedup vs baseline: 8.1793x; 2.6294x over previous
#include <cuda_runtime.h>
#include <cuda_fp16.h>
#include <cstdint>

// Problem constants
#define PB   2
#define PN   150000
#define PC   64
#define PD   128
#define PD3  (PD*PD*PD)
#define BN   (PB*PN)
#define TOTE (BN*PC)
#define EPSV 1e-4f
#define STAT_BLOCKS 1024

#define TILE_M 256
#define NTILES ((PN + TILE_M - 1) / TILE_M)   // 586

// smem layout (fp16 tiles, 144B padded row stride)
#define SA_STRIDE_B 144                        // 64 halves (128B) + 16B pad
#define SA_BYTES    (TILE_M * SA_STRIDE_B)     // 36864
#define SW_BYTES    (64 * SA_STRIDE_B)         // 9216
#define OFF_A(s)    ((s) * SA_BYTES)
#define OFF_W(s)    (2 * SA_BYTES + (s) * SW_BYTES)
#define OFF_FLAG    (2 * SA_BYTES + 2 * SW_BYTES)   // 92160
#define SMEM_TOTAL  (OFF_FLAG + 128)                // 92288

// ---------------- device scratch (no allocation allowed) ----------------
__device__ int    g_lut[PB * PD3];
__device__ int    g_nbr[27 * BN];
__device__ float  g_tmp2[(size_t)BN * PC];          // conv1 output (f32)
__device__ __half g_h16[(size_t)BN * PC];           // bn_relu output (fp16 conv input)
__device__ __half g_wt16[4 * 27 * PC * PC];         // W^T fp16 [conv*27][cout][cin]
__device__ float  g_part[2 * STAT_BLOCKS * PC];
__device__ float  g_scale[PC];
__device__ float  g_shift[PC];

// ---------------- helpers ----------------
__device__ __forceinline__ uint32_t smem_u32(const void* p) {
    uint32_t a;
    asm("{ .reg .u64 t; cvta.to.shared.u64 t, %1; cvt.u32.u64 %0, t; }" : "=r"(a) : "l"(p));
    return a;
}

// ---------------- prep kernels ----------------
__global__ void fill_lut_kernel() {
    int i = blockIdx.x * blockDim.x + threadIdx.x;
    if (i < PB * PD3) g_lut[i] = -1;
}
__global__ void scatter_lut_kernel(const int* __restrict__ pos) {
    int i = blockIdx.x * blockDim.x + threadIdx.x;
    if (i >= BN) return;
    int b = i / PN;
    int code = (pos[3 * i] * PD + pos[3 * i + 1]) * PD + pos[3 * i + 2];
    g_lut[b * PD3 + code] = i - b * PN;
}
__global__ void build_nbr_kernel(const int* __restrict__ pos) {
    int i = blockIdx.x * blockDim.x + threadIdx.x;
    if (i >= BN) return;
    int b = i / PN;
    int px = pos[3 * i], py = pos[3 * i + 1], pz = pos[3 * i + 2];
    const int* lutb = g_lut + b * PD3;
#pragma unroll
    for (int k = 0; k < 27; k++) {
        int nx = px + k / 9 - 1, ny = py + (k / 3) % 3 - 1, nz = pz + k % 3 - 1;
        int nidx = -1;
        if (((unsigned)nx < PD) & ((unsigned)ny < PD) & ((unsigned)nz < PD))
            nidx = lutb[(nx * PD + ny) * PD + nz];
        g_nbr[k * BN + i] = nidx;
    }
}
// W^T fp16: g_wt16[mat][cout][cin] from Ws[mat][cin][cout]
__global__ void wprep_kernel(const float* __restrict__ Ws) {
    int i = blockIdx.x * blockDim.x + threadIdx.x;
    if (i >= 4 * 27 * 4096) return;
    int mat = i >> 12;
    int co  = (i >> 6) & 63;
    int ci  = i & 63;
    g_wt16[i] = __float2half_rn(Ws[mat * 4096 + ci * 64 + co]);
}

// ---------------- BN ----------------
__global__ void stats_kernel(const float* __restrict__ x) {
    __shared__ float red[2048];
    int t = threadIdx.x;
    size_t gid = (size_t)blockIdx.x * 256 + t;
    const float4* x4 = (const float4*)x;
    float4 s = make_float4(0, 0, 0, 0), q = make_float4(0, 0, 0, 0);
    for (size_t i = gid; i < (size_t)TOTE / 4; i += (size_t)256 * STAT_BLOCKS) {
        float4 v = x4[i];
        s.x += v.x; s.y += v.y; s.z += v.z; s.w += v.w;
        q.x += v.x * v.x; q.y += v.y * v.y; q.z += v.z * v.z; q.w += v.w * v.w;
    }
    red[t * 4 + 0] = s.x; red[t * 4 + 1] = s.y; red[t * 4 + 2] = s.z; red[t * 4 + 3] = s.w;
    red[1024 + t * 4 + 0] = q.x; red[1024 + t * 4 + 1] = q.y;
    red[1024 + t * 4 + 2] = q.z; red[1024 + t * 4 + 3] = q.w;
    __syncthreads();
    if (t < 64) {
        int comp = t & 3, grp = t >> 2;
        float S = 0.f, Q = 0.f;
#pragma unroll
        for (int m = 0; m < 16; m++) {
            int o = grp + m * 16;
            S += red[o * 4 + comp];
            Q += red[1024 + o * 4 + comp];
        }
        g_part[blockIdx.x * 64 + t] = S;
        g_part[STAT_BLOCKS * 64 + blockIdx.x * 64 + t] = Q;
    }
}

__global__ void finalize_stats_kernel(const float* __restrict__ gamma,
                                      const float* __restrict__ beta) {
    __shared__ float r[512];
    int t = threadIdx.x;            // 256
    int c = t & 63, seg = t >> 6;
    float S = 0.f, Q = 0.f;
    for (int b = seg * 256; b < (seg + 1) * 256; b++) {
        S += g_part[b * 64 + c];
        Q += g_part[STAT_BLOCKS * 64 + b * 64 + c];
    }
    r[t] = S; r[256 + t] = Q;
    __syncthreads();
    if (t < 64) {
        float s = r[t] + r[t + 64] + r[t + 128] + r[t + 192];
        float q = r[256 + t] + r[256 + t + 64] + r[256 + t + 128] + r[256 + t + 192];
        const float inv = 1.0f / (float)BN;
        float mu = s * inv;
        float var = q * inv - mu * mu;
        float rstd = rsqrtf(var + EPSV);
        float sc = rstd * gamma[t];
        g_scale[t] = sc;
        g_shift[t] = beta[t] - mu * sc;
    }
}

// bn_relu + convert to fp16 (conv input). 8 channels per thread.
__global__ void bnrelu_kernel(const float* __restrict__ x, __half* __restrict__ y) {
    int i = blockIdx.x * blockDim.x + threadIdx.x;
    if (i >= TOTE / 8) return;
    const float4* x4 = (const float4*)x;
    float4 v0 = x4[2 * i], v1 = x4[2 * i + 1];
    int c8 = i & 7;
    float4 sc0 = ((const float4*)g_scale)[2 * c8], sc1 = ((const float4*)g_scale)[2 * c8 + 1];
    float4 sh0 = ((const float4*)g_shift)[2 * c8], sh1 = ((const float4*)g_shift)[2 * c8 + 1];
    __half2 h[4];
    h[0] = __floats2half2_rn(fmaxf(fmaf(v0.x, sc0.x, sh0.x), 0.f),
                             fmaxf(fmaf(v0.y, sc0.y, sh0.y), 0.f));
    h[1] = __floats2half2_rn(fmaxf(fmaf(v0.z, sc0.z, sh0.z), 0.f),
                             fmaxf(fmaf(v0.w, sc0.w, sh0.w), 0.f));
    h[2] = __floats2half2_rn(fmaxf(fmaf(v1.x, sc1.x, sh1.x), 0.f),
                             fmaxf(fmaf(v1.y, sc1.y, sh1.y), 0.f));
    h[3] = __floats2half2_rn(fmaxf(fmaf(v1.z, sc1.z, sh1.z), 0.f),
                             fmaxf(fmaf(v1.w, sc1.w, sh1.w), 0.f));
    ((uint4*)y)[i] = *(uint4*)h;
}

// ---------------- conv via fp16 mma.sync m16n8k16 + ldmatrix ----------------
// CTA: 256 points x 64 out-ch, 512 threads = 16 warps (8 M x 2 N).
// Warp tile 32x32. A/W fp16 double-buffered via cp.async (zero-fill invalid).
__global__ __launch_bounds__(512, 2) void conv_mma_kernel(
    const __half* __restrict__ h, const __half* __restrict__ wt,
    float* __restrict__ out, const float* __restrict__ addsrc) {
    extern __shared__ char smem[];
    const uint32_t sbase = smem_u32(smem);
    const int tid  = threadIdx.x;
    const int lane = tid & 31;
    const int wid  = tid >> 5;
    const int b    = blockIdx.y;
    const int pt0  = blockIdx.x * TILE_M;
    const __half* hb = h + (size_t)b * PN * PC;
    int* flags = (int*)(smem + OFF_FLAG);   // [2][16], one per 16-row group

    const int warp_m = wid >> 1;    // 0..7
    const int warp_n = wid & 1;     // 0..1
    const int g   = lane >> 2;
    const int tig = lane & 3;

    float acc[2][4][4];
#pragma unroll
    for (int mt = 0; mt < 2; mt++)
#pragma unroll
        for (int nt = 0; nt < 4; nt++)
#pragma unroll
            for (int e = 0; e < 4; e++) acc[mt][nt][e] = 0.f;

    // ldmatrix lane addresses (byte offsets within a stage)
    // A: row = warp_m*32 + mt*16 + (lane&15), col-16B = lane>>4
    const uint32_t a_row = (uint32_t)(warp_m * 32 + (lane & 15));
    const uint32_t a_laddr0 = a_row * SA_STRIDE_B + ((uint32_t)(lane >> 4)) * 16;
    // B(W^T): row n = warp_n*32 + pair*16 + ((lane>>4)&1)*8 + (lane&7), col-16B = (lane>>3)&1
    const uint32_t b_row = (uint32_t)(warp_n * 32 + ((lane >> 4) & 1) * 8 + (lane & 7));
    const uint32_t b_laddr0 = b_row * SA_STRIDE_B + (((uint32_t)(lane >> 3)) & 1) * 16;

    auto issue = [&](int k, int s) {
        int row  = tid >> 1;
        int p    = pt0 + row;
        int nidx = (p < PN) ? g_nbr[k * BN + b * PN + p] : -1;
        unsigned msk = __ballot_sync(0xffffffffu, nidx >= 0);
        if (lane == 0) flags[s * 16 + wid] = (msk != 0u);
        const char* src = (const char*)(hb + (size_t)(nidx < 0 ? 0 : nidx) * PC)
                          + (tid & 1) * 64;
        uint32_t dst = sbase + OFF_A(s) + row * SA_STRIDE_B + (tid & 1) * 64;
        int ssz = (nidx >= 0) ? 16 : 0;
#pragma unroll
        for (int c = 0; c < 4; c++)
            asm volatile("cp.async.ca.shared.global [%0], [%1], 16, %2;"
                         :: "r"(dst + c * 16), "l"(src + c * 16), "r"(ssz));
        // W^T: 64 rows x 128B = 512 16B chunks, one per thread
        {
            int wrow = tid >> 3, wc = tid & 7;
            const char* ws = (const char*)(wt + (size_t)k * 4096) + wrow * 128 + wc * 16;
            uint32_t wdst = sbase + OFF_W(s) + wrow * SA_STRIDE_B + wc * 16;
            asm volatile("cp.async.ca.shared.global [%0], [%1], 16;" :: "r"(wdst), "l"(ws));
        }
        asm volatile("cp.async.commit_group;" ::: "memory");
    };

    auto compute = [&](int s) {
        const int f0 = flags[s * 16 + 2 * warp_m];
        const int f1 = flags[s * 16 + 2 * warp_m + 1];
        if (!(f0 | f1)) return;
        const uint32_t abase = sbase + OFF_A(s) + a_laddr0;
        const uint32_t bbase = sbase + OFF_W(s) + b_laddr0;
#pragma unroll
        for (int k16 = 0; k16 < 4; k16++) {
            uint32_t bw[8];
            // two x4 loads cover n32 x k16 for this warp's N half
            asm volatile("ldmatrix.sync.aligned.m8n8.x4.shared.b16 {%0,%1,%2,%3}, [%4];"
                         : "=r"(bw[0]), "=r"(bw[1]), "=r"(bw[2]), "=r"(bw[3])
                         : "r"(bbase + k16 * 32));
            asm volatile("ldmatrix.sync.aligned.m8n8.x4.shared.b16 {%0,%1,%2,%3}, [%4];"
                         : "=r"(bw[4]), "=r"(bw[5]), "=r"(bw[6]), "=r"(bw[7])
                         : "r"(bbase + 16 * SA_STRIDE_B + k16 * 32));
#pragma unroll
            for (int mt = 0; mt < 2; mt++) {
                if (!(mt ? f1 : f0)) continue;
                uint32_t a[4];
                asm volatile("ldmatrix.sync.aligned.m8n8.x4.shared.b16 {%0,%1,%2,%3}, [%4];"
                             : "=r"(a[0]), "=r"(a[1]), "=r"(a[2]), "=r"(a[3])
                             : "r"(abase + mt * (16 * SA_STRIDE_B) + k16 * 32));
#pragma unroll
                for (int nt = 0; nt < 4; nt++)
                    asm volatile(
                        "mma.sync.aligned.m16n8k16.row.col.f32.f16.f16.f32 "
                        "{%0,%1,%2,%3}, {%4,%5,%6,%7}, {%8,%9}, {%0,%1,%2,%3};"
                        : "+f"(acc[mt][nt][0]), "+f"(acc[mt][nt][1]),
                          "+f"(acc[mt][nt][2]), "+f"(acc[mt][nt][3])
                        : "r"(a[0]), "r"(a[1]), "r"(a[2]), "r"(a[3]),
                          "r"(bw[nt * 2]), "r"(bw[nt * 2 + 1]));
            }
        }
    };

    issue(0, 0);
    for (int k = 0; k < 27; k++) {
        const int s = k & 1;
        if (k + 1 < 27) {
            issue(k + 1, s ^ 1);
            asm volatile("cp.async.wait_group 1;" ::: "memory");
        } else {
            asm volatile("cp.async.wait_group 0;" ::: "memory");
        }
        __syncthreads();
        compute(s);
        __syncthreads();
    }

    // epilogue: 32x32 per warp, optional residual add
    const bool doadd = (addsrc != nullptr);
#pragma unroll
    for (int mt = 0; mt < 2; mt++) {
#pragma unroll
        for (int half = 0; half < 2; half++) {
            int r = warp_m * 32 + mt * 16 + half * 8 + g;
            int p = pt0 + r;
            if (p < PN) {
                size_t rowoff = ((size_t)b * PN + p) * PC + warp_n * 32 + 2 * tig;
                float* orow = out + rowoff;
#pragma unroll
                for (int nt = 0; nt < 4; nt++) {
                    float2 v;
                    v.x = acc[mt][nt][half * 2 + 0];
                    v.y = acc[mt][nt][half * 2 + 1];
                    if (doadd) {
                        float2 av = *(const float2*)(addsrc + rowoff + nt * 8);
                        v.x += av.x; v.y += av.y;
                    }
                    *(float2*)(orow + nt * 8) = v;
                }
            }
        }
    }
}

// ---------------- host orchestration ----------------
static void run_bn(const float* xin, __half* yout, const float* gamma, const float* beta) {
    stats_kernel<<<STAT_BLOCKS, 256>>>(xin);
    finalize_stats_kernel<<<1, 256>>>(gamma, beta);
    bnrelu_kernel<<<(TOTE / 8 + 255) / 256, 256>>>(xin, yout);
}

extern "C" void kernel_launch(void* const* d_in, const int* in_sizes, int n_in,
                              void* d_out, int out_size) {
    const float* feats  = (const float*)d_in[0];
    const float* Ws     = (const float*)d_in[1];
    const float* gammas = (const float*)d_in[2];
    const float* betas  = (const float*)d_in[3];
    const int*   pos    = (const int*)d_in[4];
    float* x = (float*)d_out;

    float* tmp2; __half *h16, *wt16;
    cudaGetSymbolAddress((void**)&tmp2, g_tmp2);
    cudaGetSymbolAddress((void**)&h16, g_h16);
    cudaGetSymbolAddress((void**)&wt16, g_wt16);

    cudaFuncSetAttribute(conv_mma_kernel, cudaFuncAttributeMaxDynamicSharedMemorySize,
                         SMEM_TOTAL);

    cudaMemcpyAsync(x, feats, (size_t)TOTE * sizeof(float), cudaMemcpyDeviceToDevice, 0);

    fill_lut_kernel<<<(PB * PD3 + 1023) / 1024, 1024>>>();
    scatter_lut_kernel<<<(BN + 255) / 256, 256>>>(pos);
    build_nbr_kernel<<<(BN + 255) / 256, 256>>>(pos);
    wprep_kernel<<<(4 * 27 * 4096 + 255) / 256, 256>>>(Ws);

    dim3 cgrid(NTILES, PB);

    for (int blk = 0; blk < 2; blk++) {
        run_bn(x, h16, gammas + (2 * blk) * PC, betas + (2 * blk) * PC);
        conv_mma_kernel<<<cgrid, 512, SMEM_TOTAL>>>(
            h16, wt16 + (size_t)(2 * blk) * 27 * 4096, tmp2, nullptr);
        run_bn(tmp2, h16, gammas + (2 * blk + 1) * PC, betas + (2 * blk + 1) * PC);
        conv_mma_kernel<<<cgrid, 512, SMEM_TOTAL>>>(
            h16, wt16 + (size_t)(2 * blk + 1) * 27 * 4096, x, x);
    }
}

// round 5
// speedup vs baseline: 10.1672x; 1.2430x over previous
#include <cuda_runtime.h>
#include <cuda_fp16.h>
#include <cstdint>

// Problem constants
#define PB   2
#define PN   150000
#define PC   64
#define PD   128
#define PD3  (PD*PD*PD)
#define BN   (PB*PN)
#define TOTE (BN*PC)
#define EPSV 1e-4f
#define STAT_BLOCKS 1024

#define TILE_M 256
#define NTILES ((PN + TILE_M - 1) / TILE_M)   // 586

// smem layout (bytes) for sparse conv kernel
#define ACC_STRIDE 66                          // floats, padded
#define OFF_ACC   0                            // 256*66*4 = 67584
#define OFF_A     67584                        // 2 stages x 64 rows x 144B = 18432
#define OFF_W     86016                        // 2 stages x 64 rows x 144B = 18432
#define OFF_LIST  104448                       // 2 x 64 ints = 512
#define OFF_WCNT  104960                       // 8 ints
#define SMEM_SP   105216

// ---------------- device scratch (no allocation allowed) ----------------
__device__ int    g_lut[PB * PD3];
__device__ int    g_nbr[27 * BN];
__device__ float  g_tmp2[(size_t)BN * PC];          // conv1 output (f32)
__device__ __half g_h16[(size_t)BN * PC];           // bn_relu output (fp16 conv input)
__device__ __half g_wt16[4 * 27 * PC * PC];         // W^T fp16 [conv*27][cout][cin]
__device__ float  g_part[2 * STAT_BLOCKS * PC];
__device__ float  g_scale[PC];
__device__ float  g_shift[PC];

// ---------------- helpers ----------------
__device__ __forceinline__ uint32_t smem_u32(const void* p) {
    uint32_t a;
    asm("{ .reg .u64 t; cvta.to.shared.u64 t, %1; cvt.u32.u64 %0, t; }" : "=r"(a) : "l"(p));
    return a;
}

// ---------------- prep kernels ----------------
__global__ void fill_lut_kernel() {
    int i = blockIdx.x * blockDim.x + threadIdx.x;
    if (i < PB * PD3) g_lut[i] = -1;
}
__global__ void scatter_lut_kernel(const int* __restrict__ pos) {
    int i = blockIdx.x * blockDim.x + threadIdx.x;
    if (i >= BN) return;
    int b = i / PN;
    int code = (pos[3 * i] * PD + pos[3 * i + 1]) * PD + pos[3 * i + 2];
    g_lut[b * PD3 + code] = i - b * PN;
}
__global__ void build_nbr_kernel(const int* __restrict__ pos) {
    int i = blockIdx.x * blockDim.x + threadIdx.x;
    if (i >= BN) return;
    int b = i / PN;
    int px = pos[3 * i], py = pos[3 * i + 1], pz = pos[3 * i + 2];
    const int* lutb = g_lut + b * PD3;
#pragma unroll
    for (int k = 0; k < 27; k++) {
        int nx = px + k / 9 - 1, ny = py + (k / 3) % 3 - 1, nz = pz + k % 3 - 1;
        int nidx = -1;
        if (((unsigned)nx < PD) & ((unsigned)ny < PD) & ((unsigned)nz < PD))
            nidx = lutb[(nx * PD + ny) * PD + nz];
        g_nbr[k * BN + i] = nidx;
    }
}
// W^T fp16: g_wt16[mat][cout][cin] from Ws[mat][cin][cout]
__global__ void wprep_kernel(const float* __restrict__ Ws) {
    int i = blockIdx.x * blockDim.x + threadIdx.x;
    if (i >= 4 * 27 * 4096) return;
    int mat = i >> 12;
    int co  = (i >> 6) & 63;
    int ci  = i & 63;
    g_wt16[i] = __float2half_rn(Ws[mat * 4096 + ci * 64 + co]);
}

// ---------------- BN ----------------
__global__ void stats_kernel(const float* __restrict__ x) {
    __shared__ float red[2048];
    int t = threadIdx.x;
    size_t gid = (size_t)blockIdx.x * 256 + t;
    const float4* x4 = (const float4*)x;
    float4 s = make_float4(0, 0, 0, 0), q = make_float4(0, 0, 0, 0);
    for (size_t i = gid; i < (size_t)TOTE / 4; i += (size_t)256 * STAT_BLOCKS) {
        float4 v = x4[i];
        s.x += v.x; s.y += v.y; s.z += v.z; s.w += v.w;
        q.x += v.x * v.x; q.y += v.y * v.y; q.z += v.z * v.z; q.w += v.w * v.w;
    }
    red[t * 4 + 0] = s.x; red[t * 4 + 1] = s.y; red[t * 4 + 2] = s.z; red[t * 4 + 3] = s.w;
    red[1024 + t * 4 + 0] = q.x; red[1024 + t * 4 + 1] = q.y;
    red[1024 + t * 4 + 2] = q.z; red[1024 + t * 4 + 3] = q.w;
    __syncthreads();
    if (t < 64) {
        int comp = t & 3, grp = t >> 2;
        float S = 0.f, Q = 0.f;
#pragma unroll
        for (int m = 0; m < 16; m++) {
            int o = grp + m * 16;
            S += red[o * 4 + comp];
            Q += red[1024 + o * 4 + comp];
        }
        g_part[blockIdx.x * 64 + t] = S;
        g_part[STAT_BLOCKS * 64 + blockIdx.x * 64 + t] = Q;
    }
}

__global__ void finalize_stats_kernel(const float* __restrict__ gamma,
                                      const float* __restrict__ beta) {
    __shared__ float r[512];
    int t = threadIdx.x;            // 256
    int c = t & 63, seg = t >> 6;
    float S = 0.f, Q = 0.f;
    for (int b = seg * 256; b < (seg + 1) * 256; b++) {
        S += g_part[b * 64 + c];
        Q += g_part[STAT_BLOCKS * 64 + b * 64 + c];
    }
    r[t] = S; r[256 + t] = Q;
    __syncthreads();
    if (t < 64) {
        float s = r[t] + r[t + 64] + r[t + 128] + r[t + 192];
        float q = r[256 + t] + r[256 + t + 64] + r[256 + t + 128] + r[256 + t + 192];
        const float inv = 1.0f / (float)BN;
        float mu = s * inv;
        float var = q * inv - mu * mu;
        float rstd = rsqrtf(var + EPSV);
        float sc = rstd * gamma[t];
        g_scale[t] = sc;
        g_shift[t] = beta[t] - mu * sc;
    }
}

__global__ void bnrelu_kernel(const float* __restrict__ x, __half* __restrict__ y) {
    int i = blockIdx.x * blockDim.x + threadIdx.x;
    if (i >= TOTE / 8) return;
    const float4* x4 = (const float4*)x;
    float4 v0 = x4[2 * i], v1 = x4[2 * i + 1];
    int c8 = i & 7;
    float4 sc0 = ((const float4*)g_scale)[2 * c8], sc1 = ((const float4*)g_scale)[2 * c8 + 1];
    float4 sh0 = ((const float4*)g_shift)[2 * c8], sh1 = ((const float4*)g_shift)[2 * c8 + 1];
    __half2 h[4];
    h[0] = __floats2half2_rn(fmaxf(fmaf(v0.x, sc0.x, sh0.x), 0.f),
                             fmaxf(fmaf(v0.y, sc0.y, sh0.y), 0.f));
    h[1] = __floats2half2_rn(fmaxf(fmaf(v0.z, sc0.z, sh0.z), 0.f),
                             fmaxf(fmaf(v0.w, sc0.w, sh0.w), 0.f));
    h[2] = __floats2half2_rn(fmaxf(fmaf(v1.x, sc1.x, sh1.x), 0.f),
                             fmaxf(fmaf(v1.y, sc1.y, sh1.y), 0.f));
    h[3] = __floats2half2_rn(fmaxf(fmaf(v1.z, sc1.z, sh1.z), 0.f),
                             fmaxf(fmaf(v1.w, sc1.w, sh1.w), 0.f));
    ((uint4*)y)[i] = *(uint4*)h;
}

// ---------------- sparse conv: gather-compact-GEMM-scatter ----------------
// CTA: 256 points, 256 threads (8 warps). f32 accumulators in SMEM.
// Per tap: ballot-compact valid pairs -> <=64-row chunks -> cp.async gather ->
// m16n8k16 MMA (warp w owns out-col slice n8=w) -> scatter-add into acc.
__global__ __launch_bounds__(256, 2) void conv_sp_kernel(
    const __half* __restrict__ h, const __half* __restrict__ wt,
    float* __restrict__ out, const float* __restrict__ addsrc) {
    extern __shared__ char smem[];
    const uint32_t sbase = smem_u32(smem);
    const int tid  = threadIdx.x;
    const int lane = tid & 31;
    const int wid  = tid >> 5;        // 0..7 = n8 slice
    const int g    = lane >> 2;
    const int tig  = lane & 3;
    const int b    = blockIdx.y;
    const int pt0  = blockIdx.x * TILE_M;
    const __half* hb = h + (size_t)b * PN * PC;

    float* accf  = (float*)smem;
    int*   slist = (int*)(smem + OFF_LIST);
    int*   swcnt = (int*)(smem + OFF_WCNT);

    // zero accumulators (256 x 66 f32)
    {
        float2 z = make_float2(0.f, 0.f);
        float2* a2 = (float2*)smem;
#pragma unroll
        for (int i = 0; i < 33; i++) a2[tid + 256 * i] = z;
    }

    const int  gp   = pt0 + tid;
    const bool inr  = gp < PN;
    const size_t gidx = (size_t)b * PN + gp;

    int pref = inr ? g_nbr[gidx] : -1;   // prefetched neighbor for tap 0
    int nidx = -1, rank = 0, cnt = 0;

    auto new_tap = [&](int k) {
        nidx = pref;
        pref = (k + 1 < 27 && inr) ? g_nbr[(size_t)(k + 1) * BN + gidx] : -1;
        unsigned msk = __ballot_sync(0xffffffffu, nidx >= 0);
        if (lane == 0) swcnt[wid] = __popc(msk);
        __syncthreads();
        int base = 0, tot = 0;
#pragma unroll
        for (int j = 0; j < 8; j++) {
            int c = swcnt[j];
            base += (j < wid) ? c : 0;
            tot += c;
        }
        rank = base + __popc(msk & ((1u << lane) - 1u));
        cnt = tot;
        __syncthreads();   // protect swcnt for next new_tap
    };

    auto issue_w = [&](int k, int ws) {
        const char* src = (const char*)(wt + (size_t)k * 4096);
#pragma unroll
        for (int j = 0; j < 2; j++) {
            int c = tid + j * 256;
            int row = c >> 3, off = (c & 7) * 16;
            uint32_t dst = sbase + OFF_W + ws * 9216 + row * 144 + off;
            asm volatile("cp.async.ca.shared.global [%0],[%1],16;"
                         :: "r"(dst), "l"(src + row * 128 + off));
        }
    };

    auto fill_list = [&](int lo, int st) {
        if (nidx >= 0 && rank >= lo && rank < lo + 64)
            slist[st * 64 + (rank - lo)] = (nidx << 8) | tid;
    };

    auto issue_a = [&](int Rc, int st) {
        int row = tid >> 2, q = tid & 3;
        if (row < Rc) {
            int e = slist[st * 64 + row];
            const char* src = (const char*)(hb + ((size_t)(e >> 8)) * PC) + q * 32;
            uint32_t dst = sbase + OFF_A + st * 9216 + row * 144 + q * 32;
            asm volatile("cp.async.ca.shared.global [%0],[%1],16;" :: "r"(dst), "l"(src));
            asm volatile("cp.async.ca.shared.global [%0],[%1],16;" :: "r"(dst + 16), "l"(src + 16));
        }
        asm volatile("cp.async.commit_group;" ::: "memory");
    };

    uint32_t bw[4][2];
    auto load_b = [&](int ws) {
#pragma unroll
        for (int j = 0; j < 4; j++) {
            uint32_t ad = sbase + OFF_W + ws * 9216 +
                          (uint32_t)(wid * 8 + (lane & 7)) * 144 + j * 32 +
                          ((lane >> 3) & 1) * 16;
            asm volatile("ldmatrix.sync.aligned.m8n8.x2.shared.b16 {%0,%1},[%2];"
                         : "=r"(bw[j][0]), "=r"(bw[j][1]) : "r"(ad));
        }
    };

    auto do_chunk = [&](int st, int Rc) {
        int Mc = (Rc + 15) >> 4;
        uint32_t ab = sbase + OFF_A + st * 9216 + (uint32_t)(lane & 15) * 144 +
                      (lane >> 4) * 16;
        for (int mt = 0; mt < Mc; mt++) {
            uint32_t a[4];
            float c[4] = {0.f, 0.f, 0.f, 0.f};
#pragma unroll
            for (int j = 0; j < 4; j++) {
                asm volatile("ldmatrix.sync.aligned.m8n8.x4.shared.b16 {%0,%1,%2,%3},[%4];"
                             : "=r"(a[0]), "=r"(a[1]), "=r"(a[2]), "=r"(a[3])
                             : "r"(ab + mt * 2304 + j * 32));
                asm volatile(
                    "mma.sync.aligned.m16n8k16.row.col.f32.f16.f16.f32 "
                    "{%0,%1,%2,%3},{%4,%5,%6,%7},{%8,%9},{%0,%1,%2,%3};"
                    : "+f"(c[0]), "+f"(c[1]), "+f"(c[2]), "+f"(c[3])
                    : "r"(a[0]), "r"(a[1]), "r"(a[2]), "r"(a[3]),
                      "r"(bw[j][0]), "r"(bw[j][1]));
            }
            int r0 = mt * 16 + g;
            if (r0 < Rc) {
                int t = slist[st * 64 + r0] & 255;
                float2* p = (float2*)(accf + (size_t)t * ACC_STRIDE + wid * 8 + 2 * tig);
                float2 v = *p; v.x += c[0]; v.y += c[1]; *p = v;
            }
            if (r0 + 8 < Rc) {
                int t = slist[st * 64 + r0 + 8] & 255;
                float2* p = (float2*)(accf + (size_t)t * ACC_STRIDE + wid * 8 + 2 * tig);
                float2 v = *p; v.x += c[2]; v.y += c[3]; *p = v;
            }
        }
    };

    // prologue: first nonempty tap (center tap guarantees existence)
    int k = 0;
    new_tap(0);
    while (cnt == 0 && k < 26) { k++; new_tap(k); }
    issue_w(k, 0);
    fill_list(0, 0);
    __syncthreads();
    int firstRc = (cnt < 64) ? cnt : 64;
    issue_a(firstRc, 0);

    int curk = k, curlo = 0, curst = 0, curWst = 0, curRc = firstRc;
    bool curNew = true;
    int tapcnt = cnt;

    while (true) {
        int nRc = 0, nst = curst ^ 1, nWst = curWst, nk = curk, nlo = 0;
        bool nNew = false;
        if (curlo + 64 < tapcnt) {
            nk = curk; nlo = curlo + 64;
            nRc = tapcnt - nlo; if (nRc > 64) nRc = 64;
            fill_list(nlo, nst);
            __syncthreads();
            issue_a(nRc, nst);
        } else {
            int k2 = curk + 1;
            while (k2 < 27) { new_tap(k2); if (cnt > 0) break; k2++; }
            if (k2 < 27) {
                nk = k2; nlo = 0; nNew = true; nWst = curWst ^ 1;
                nRc = (cnt < 64) ? cnt : 64;
                issue_w(k2, nWst);
                fill_list(0, nst);
                __syncthreads();
                issue_a(nRc, nst);
            }
        }
        if (nRc > 0) asm volatile("cp.async.wait_group 1;" ::: "memory");
        else         asm volatile("cp.async.wait_group 0;" ::: "memory");
        __syncthreads();
        if (curNew) load_b(curWst);
        do_chunk(curst, curRc);
        __syncthreads();
        if (nRc == 0) break;
        curk = nk; curlo = nlo; curst = nst; curWst = nWst; curNew = nNew; curRc = nRc;
        if (nNew) tapcnt = cnt;
    }

    // epilogue: acc -> out (+ optional residual). warp w -> rows w*32..w*32+31
    const bool doadd = (addsrc != nullptr);
    for (int r32 = 0; r32 < 32; r32++) {
        int row = wid * 32 + r32;
        int p = pt0 + row;
        if (p < PN) {
            float2 v = *(float2*)(accf + (size_t)row * ACC_STRIDE + lane * 2);
            size_t o = ((size_t)b * PN + p) * PC + lane * 2;
            if (doadd) {
                float2 a2 = *(const float2*)(addsrc + o);
                v.x += a2.x; v.y += a2.y;
            }
            *(float2*)(out + o) = v;
        }
    }
}

// ---------------- host orchestration ----------------
static void run_bn(const float* xin, __half* yout, const float* gamma, const float* beta) {
    stats_kernel<<<STAT_BLOCKS, 256>>>(xin);
    finalize_stats_kernel<<<1, 256>>>(gamma, beta);
    bnrelu_kernel<<<(TOTE / 8 + 255) / 256, 256>>>(xin, yout);
}

extern "C" void kernel_launch(void* const* d_in, const int* in_sizes, int n_in,
                              void* d_out, int out_size) {
    const float* feats  = (const float*)d_in[0];
    const float* Ws     = (const float*)d_in[1];
    const float* gammas = (const float*)d_in[2];
    const float* betas  = (const float*)d_in[3];
    const int*   pos    = (const int*)d_in[4];
    float* x = (float*)d_out;

    float* tmp2; __half *h16, *wt16;
    cudaGetSymbolAddress((void**)&tmp2, g_tmp2);
    cudaGetSymbolAddress((void**)&h16, g_h16);
    cudaGetSymbolAddress((void**)&wt16, g_wt16);

    cudaFuncSetAttribute(conv_sp_kernel, cudaFuncAttributeMaxDynamicSharedMemorySize,
                         SMEM_SP);

    fill_lut_kernel<<<(PB * PD3 + 1023) / 1024, 1024>>>();
    scatter_lut_kernel<<<(BN + 255) / 256, 256>>>(pos);
    build_nbr_kernel<<<(BN + 255) / 256, 256>>>(pos);
    wprep_kernel<<<(4 * 27 * 4096 + 255) / 256, 256>>>(Ws);

    dim3 cgrid(NTILES, PB);

    // block 0 (input = feats directly; residual add uses feats)
    run_bn(feats, h16, gammas + 0 * PC, betas + 0 * PC);
    conv_sp_kernel<<<cgrid, 256, SMEM_SP>>>(h16, wt16 + (size_t)0 * 27 * 4096, tmp2, nullptr);
    run_bn(tmp2, h16, gammas + 1 * PC, betas + 1 * PC);
    conv_sp_kernel<<<cgrid, 256, SMEM_SP>>>(h16, wt16 + (size_t)1 * 27 * 4096, x, feats);

    // block 1
    run_bn(x, h16, gammas + 2 * PC, betas + 2 * PC);
    conv_sp_kernel<<<cgrid, 256, SMEM_SP>>>(h16, wt16 + (size_t)2 * 27 * 4096, tmp2, nullptr);
    run_bn(tmp2, h16, gammas + 3 * PC, betas + 3 * PC);
    conv_sp_kernel<<<cgrid, 256, SMEM_SP>>>(h16, wt16 + (size_t)3 * 27 * 4096, x, x);
}